// round 16
// baseline (speedup 1.0000x reference)
#include <cuda_runtime.h>
#include <cuda_bf16.h>
#include <math.h>
#include <stdint.h>

// ---------------------------------------------------------------------------
// DeepSeek V3.2 sparse attention, B=1 S=2048 D=4096 H=16 DN=128 DR=64 DV=128
// Indexer chain: fp32 (FFMA2) GEMMs + fp32 indexer — per-output accumulation
//   order bit-identical to all passing rounds -> deterministic top-k mask.
// Value path: mma.sync bf16 2-term split; flash FFMA2 (mask-independent).
// R16: q-range pipelining — qi/rope/indexer/topk split into high (512..2047,
//   critical path -> flashA) and low (0..511, overlapped in flashA's shadow).
//   All kernels identical math; only row-offset params added.
// ---------------------------------------------------------------------------

#define S_ 2048
#define H_ 16
#define TOPK_ 1024

// ------------------------- fp32 scratch ------------------------------------
__device__ float g_cq   [S_ * 1536];
__device__ float g_q    [S_ * 3072];
__device__ float g_kv   [S_ * 576];
__device__ float g_krope[S_ * 64];
__device__ float g_kvb  [S_ * 4096];
__device__ float g_qi   [S_ * 2048];
__device__ float g_ki   [S_ * 128];
__device__ float g_wts  [S_ * 16];
__device__ float g_isc  [S_ * S_];
__device__ unsigned char g_mask[S_ * S_];
__device__ float g_attn [S_ * 2048];
__device__ float g_wcomb [4096 * 144];
__device__ float g_kicomb[S_ * 144];

// ------------------------- bf16 2-term split buffers ------------------------
__device__ __nv_bfloat16 g_H0 [2048*4096], g_H1 [2048*4096];
__device__ __nv_bfloat16 g_CQ0[2048*1536], g_CQ1[2048*1536];
__device__ __nv_bfloat16 g_KV0[2048*512],  g_KV1[2048*512];
__device__ __nv_bfloat16 g_AT0[2048*2048], g_AT1[2048*2048];
__device__ __nv_bfloat16 g_Wkva0[640*4096], g_Wkva1[640*4096];
__device__ __nv_bfloat16 g_Wqb0[3072*1536], g_Wqb1[3072*1536];
__device__ __nv_bfloat16 g_Wkvb0[4096*512], g_Wkvb1[4096*512];
__device__ __nv_bfloat16 g_Wo0 [4096*2048], g_Wo1 [4096*2048];

// ------------------------- streams / events (global ctor) -------------------
namespace {
struct SInit {
    cudaStream_t s1 = nullptr, s2 = nullptr;
    cudaEvent_t ev0 = nullptr, ev_cq = nullptr, ev_val = nullptr, ev_ki = nullptr;
    cudaEvent_t ev_fa = nullptr, ev_qih = nullptr, ev_tkB = nullptr, ev_fb = nullptr;
    SInit() {
        cudaStreamCreateWithFlags(&s1, cudaStreamNonBlocking);
        cudaStreamCreateWithFlags(&s2, cudaStreamNonBlocking);
        cudaEventCreateWithFlags(&ev0,    cudaEventDisableTiming);
        cudaEventCreateWithFlags(&ev_cq,  cudaEventDisableTiming);
        cudaEventCreateWithFlags(&ev_val, cudaEventDisableTiming);
        cudaEventCreateWithFlags(&ev_ki,  cudaEventDisableTiming);
        cudaEventCreateWithFlags(&ev_fa,  cudaEventDisableTiming);
        cudaEventCreateWithFlags(&ev_qih, cudaEventDisableTiming);
        cudaEventCreateWithFlags(&ev_tkB, cudaEventDisableTiming);
        cudaEventCreateWithFlags(&ev_fb,  cudaEventDisableTiming);
    }
};
SInit g_si;
}

// ------------------------- PTX helpers -------------------------------------
__device__ __forceinline__ uint32_t smem_u32(const void* p) {
    uint32_t a;
    asm("{ .reg .u64 t; cvta.to.shared.u64 t, %1; cvt.u32.u64 %0, t; }" : "=r"(a) : "l"(p));
    return a;
}
__device__ __forceinline__ void cp16(uint32_t dst, const void* src) {
    asm volatile("cp.async.cg.shared.global [%0], [%1], 16;" :: "r"(dst), "l"(src));
}
__device__ __forceinline__ void cp16z(uint32_t dst, const void* src) {
    asm volatile("cp.async.cg.shared.global [%0], [%1], 16, 0;" :: "r"(dst), "l"(src));
}
__device__ __forceinline__ void mma16816(float* d, const uint32_t* a, const uint32_t* b) {
    asm volatile("mma.sync.aligned.m16n8k16.row.col.f32.bf16.bf16.f32 "
        "{%0,%1,%2,%3}, {%4,%5,%6,%7}, {%8,%9}, {%0,%1,%2,%3};"
        : "+f"(d[0]), "+f"(d[1]), "+f"(d[2]), "+f"(d[3])
        : "r"(a[0]), "r"(a[1]), "r"(a[2]), "r"(a[3]), "r"(b[0]), "r"(b[1]));
}
__device__ __forceinline__ unsigned long long packf2(float lo, float hi) {
    unsigned long long v;
    asm("mov.b64 %0, {%1, %2};" : "=l"(v) : "f"(lo), "f"(hi));
    return v;
}
__device__ __forceinline__ void unpackf2(unsigned long long v, float& lo, float& hi) {
    asm("mov.b64 {%0, %1}, %2;" : "=f"(lo), "=f"(hi) : "l"(v));
}
__device__ __forceinline__ void ffma2(unsigned long long& d, unsigned long long a,
                                      unsigned long long b) {
    asm("fma.rn.f32x2 %0, %1, %2, %0;" : "+l"(d) : "l"(a), "l"(b));
}
__device__ __forceinline__ void mulf2(unsigned long long& d, unsigned long long a) {
    asm("mul.rn.f32x2 %0, %0, %1;" : "+l"(d) : "l"(a));
}

// ------------------------- fp32 GEMM (FFMA2, pipelined, bit-exact) ----------
#define FST 20
#define F_ASZ (128*FST)
#define F_BSZ (16*128)
#define F_STG (F_ASZ + F_BSZ)
__global__ void __launch_bounds__(256, 2) gemm_f32(
    const float* __restrict__ A, const float* __restrict__ B,
    float* __restrict__ C, int M, int N, int K, int lda, int m_off)
{
    extern __shared__ float smf[];
    const uint32_t sbase = smem_u32(smf);
    const int tid = threadIdx.x;
    const int tx = tid & 15, ty = tid >> 4;
    const int m0 = m_off + blockIdx.y * 128;
    const int n0 = blockIdx.x * 128;

    unsigned long long acc[8][4];
#pragma unroll
    for (int i = 0; i < 8; i++)
#pragma unroll
        for (int j = 0; j < 4; j++) acc[i][j] = 0ull;

    auto issue = [&](int k0, int st) {
#pragma unroll
        for (int i = 0; i < 2; i++) {
            int e = tid + i*256;
            int row = e >> 2, seg = e & 3;
            const float* src = &A[(size_t)(m0+row)*lda + k0 + seg*4];
            uint32_t dst = sbase + (uint32_t)(st*F_STG + row*FST + seg*4)*4;
            cp16(dst, src);
        }
#pragma unroll
        for (int i = 0; i < 2; i++) {
            int e = tid + i*256;
            int kk = e >> 5, n4 = e & 31;
            int col = n0 + n4*4;
            const float* src = &B[(size_t)(k0+kk)*N + col];
            uint32_t dst = sbase + (uint32_t)(st*F_STG + F_ASZ + kk*128 + n4*4)*4;
            if (col < N) cp16(dst, src);
            else         cp16z(dst, B);
        }
        asm volatile("cp.async.commit_group;" ::: "memory");
    };

    const int nch = K >> 4;
    issue(0, 0);
    for (int ch = 0; ch < nch; ch++) {
        const int st = ch & 1;
        if (ch + 1 < nch) {
            issue((ch + 1) << 4, st ^ 1);
            asm volatile("cp.async.wait_group 1;" ::: "memory");
        } else {
            asm volatile("cp.async.wait_group 0;" ::: "memory");
        }
        __syncthreads();
        const float* As = smf + st*F_STG;
        const float* Bs = smf + st*F_STG + F_ASZ;
#pragma unroll
        for (int kk2 = 0; kk2 < 16; kk2 += 2) {
            float2 a2[8];
#pragma unroll
            for (int i = 0; i < 8; i++)
                a2[i] = *reinterpret_cast<const float2*>(&As[(ty*8+i)*FST + kk2]);
#pragma unroll
            for (int u = 0; u < 2; u++) {
                const int kk = kk2 + u;
                unsigned long long ap[8], bp[4];
#pragma unroll
                for (int i = 0; i < 8; i++) {
                    float a = u ? a2[i].y : a2[i].x;
                    ap[i] = packf2(a, a);
                }
                float4 b0 = *reinterpret_cast<const float4*>(&Bs[kk*128 + tx*8]);
                float4 b1 = *reinterpret_cast<const float4*>(&Bs[kk*128 + tx*8 + 4]);
                bp[0] = packf2(b0.x, b0.y); bp[1] = packf2(b0.z, b0.w);
                bp[2] = packf2(b1.x, b1.y); bp[3] = packf2(b1.z, b1.w);
#pragma unroll
                for (int i = 0; i < 8; i++)
#pragma unroll
                    for (int j = 0; j < 4; j++) ffma2(acc[i][j], ap[i], bp[j]);
            }
        }
        __syncthreads();
    }
#pragma unroll
    for (int i = 0; i < 8; i++) {
        int row = m0 + ty*8 + i;
#pragma unroll
        for (int j = 0; j < 4; j++) {
            int col = n0 + tx*8 + j*2;
            float lo, hi;
            unpackf2(acc[i][j], lo, hi);
            *reinterpret_cast<float2*>(&C[(size_t)row*N + col]) = make_float2(lo, hi);
        }
    }
}

// ------------------ fp32 GEMM, 32-row tile (skinny N), FFMA2 ----------------
__global__ void __launch_bounds__(256, 2) gemm_f32_m32(
    const float* __restrict__ A, const float* __restrict__ B,
    float* __restrict__ C, int M, int N, int K, int lda, int ldc)
{
    __shared__ float As[2][32*FST];
    __shared__ float Bs[2][16*128];
    const int tid = threadIdx.x;
    const int tx = tid & 15, ty = tid >> 4;
    const int m0 = blockIdx.y * 32;
    const int n0 = blockIdx.x * 128;

    unsigned long long acc[2][4];
#pragma unroll
    for (int i = 0; i < 2; i++)
#pragma unroll
        for (int j = 0; j < 4; j++) acc[i][j] = 0ull;

    auto issue = [&](int k0, int st) {
        if (tid < 128) {
            int row = tid >> 2, seg = tid & 3;
            const float* src = &A[(size_t)(m0+row)*lda + k0 + seg*4];
            cp16(smem_u32(&As[st][row*FST + seg*4]), src);
        }
#pragma unroll
        for (int i = 0; i < 2; i++) {
            int e = tid + i*256;
            int kk = e >> 5, n4 = e & 31;
            int col = n0 + n4*4;
            const float* src = &B[(size_t)(k0+kk)*N + col];
            uint32_t dst = smem_u32(&Bs[st][kk*128 + n4*4]);
            if (col < N) cp16(dst, src);
            else         cp16z(dst, B);
        }
        asm volatile("cp.async.commit_group;" ::: "memory");
    };

    const int nch = K >> 4;
    issue(0, 0);
    for (int ch = 0; ch < nch; ch++) {
        const int st = ch & 1;
        if (ch + 1 < nch) {
            issue((ch + 1) << 4, st ^ 1);
            asm volatile("cp.async.wait_group 1;" ::: "memory");
        } else {
            asm volatile("cp.async.wait_group 0;" ::: "memory");
        }
        __syncthreads();
#pragma unroll
        for (int kk = 0; kk < 16; kk++) {
            float a0 = As[st][(ty*2+0)*FST + kk];
            float a1 = As[st][(ty*2+1)*FST + kk];
            unsigned long long ap0 = packf2(a0, a0), ap1 = packf2(a1, a1);
            float4 b0 = *reinterpret_cast<const float4*>(&Bs[st][kk*128 + tx*8]);
            float4 b1 = *reinterpret_cast<const float4*>(&Bs[st][kk*128 + tx*8 + 4]);
            unsigned long long bp[4] = {packf2(b0.x,b0.y), packf2(b0.z,b0.w),
                                        packf2(b1.x,b1.y), packf2(b1.z,b1.w)};
#pragma unroll
            for (int j = 0; j < 4; j++) { ffma2(acc[0][j], ap0, bp[j]); ffma2(acc[1][j], ap1, bp[j]); }
        }
        __syncthreads();
    }
#pragma unroll
    for (int i = 0; i < 2; i++) {
        int row = m0 + ty*2 + i;
#pragma unroll
        for (int j = 0; j < 4; j++) {
            int col = n0 + tx*8 + j*2;
            float lo, hi;
            unpackf2(acc[i][j], lo, hi);
            if (col < N)     C[(size_t)row*ldc + col]     = lo;
            if (col + 1 < N) C[(size_t)row*ldc + col + 1] = hi;
        }
    }
}

__global__ void pack_wik(const float* __restrict__ wk, const float* __restrict__ wp,
                         float* __restrict__ comb)
{
    int i = blockIdx.x * 256 + threadIdx.x;
    if (i >= 4096*144) return;
    int k = i / 144, c = i - k*144;
    comb[i] = (c < 128) ? wk[(size_t)k*128 + c] : wp[(size_t)k*16 + (c-128)];
}

// ------------------------- conversions -------------------------------------
__global__ void act_conv(const float* __restrict__ X, __nv_bfloat16* __restrict__ hi,
                         __nv_bfloat16* __restrict__ lo, int M, int Khalf, int lda)
{
    int i = blockIdx.x * 256 + threadIdx.x;
    if (i >= M * Khalf) return;
    int m = i / Khalf, kp = i - m * Khalf;
    float2 v = *reinterpret_cast<const float2*>(&X[(size_t)m*lda + kp*2]);
    __nv_bfloat16 h0 = __float2bfloat16(v.x), h1 = __float2bfloat16(v.y);
    __nv_bfloat16 l0 = __float2bfloat16(v.x - __bfloat162float(h0));
    __nv_bfloat16 l1 = __float2bfloat16(v.y - __bfloat162float(h1));
    size_t o = (size_t)m * (Khalf*2) + kp*2;
    *reinterpret_cast<__nv_bfloat162*>(&hi[o]) = __halves2bfloat162(h0, h1);
    *reinterpret_cast<__nv_bfloat162*>(&lo[o]) = __halves2bfloat162(l0, l1);
}

__global__ void wconv_t(const float* __restrict__ W, __nv_bfloat16* __restrict__ hi,
                        __nv_bfloat16* __restrict__ lo, int K, int N)
{
    __shared__ float t[32][33];
    int n0 = blockIdx.x*32, k0 = blockIdx.y*32;
    int tx = threadIdx.x, ty = threadIdx.y;
#pragma unroll
    for (int r = 0; r < 4; r++) {
        int k = k0 + ty + r*8, n = n0 + tx;
        t[tx][ty + r*8] = (n < N) ? W[(size_t)k*N + n] : 0.f;
    }
    __syncthreads();
#pragma unroll
    for (int r = 0; r < 4; r++) {
        int n = n0 + ty + r*8, k = k0 + tx;
        float x = t[ty + r*8][tx];
        __nv_bfloat16 h = __float2bfloat16(x);
        hi[(size_t)n*K + k] = h;
        lo[(size_t)n*K + k] = __float2bfloat16(x - __bfloat162float(h));
    }
}

// ------------------------- mma.sync 2-term GEMM ----------------------------
#define AST 40
#define BUF_E (128*AST)
__global__ void __launch_bounds__(256) gemm_mma2(
    const __nv_bfloat16* __restrict__ A0, const __nv_bfloat16* __restrict__ A1,
    const __nv_bfloat16* __restrict__ B0, const __nv_bfloat16* __restrict__ B1,
    float* __restrict__ C, int N, int K, int ldc)
{
    constexpr int NB = 4;
    extern __shared__ __nv_bfloat16 smb[];
    const uint32_t sbase = smem_u32(smb);
    const int tid = threadIdx.x;
    const int wid = tid >> 5, lane = tid & 31;
    const int wr = wid >> 2, wc = wid & 3;
    const int m0 = blockIdx.y * 128;
    const int n0 = blockIdx.x * 128;
    const int g = lane >> 2, tq = lane & 3;

    float acc[4][4][4];
#pragma unroll
    for (int mt = 0; mt < 4; mt++)
#pragma unroll
        for (int nt = 0; nt < 4; nt++)
#pragma unroll
            for (int i = 0; i < 4; i++) acc[mt][nt][i] = 0.f;

    const __nv_bfloat16* srcs[NB] = {A0, A1, B0, B1};
    const int nch = K >> 5;

    auto issue = [&](int ch, int st) {
        const int kb = ch << 5;
#pragma unroll
        for (int i = 0; i < NB*2; i++) {
            int e = tid + i*256;
            int buf = e >> 9;
            int r   = (e >> 2) & 127;
            int seg = e & 3;
            int grow = (buf < 2) ? (m0 + r) : (n0 + r);
            const __nv_bfloat16* gsrc = srcs[buf] + (size_t)grow*K + kb + seg*8;
            uint32_t daddr = sbase + (uint32_t)((st*NB + buf)*BUF_E + r*AST + seg*8)*2;
            cp16(daddr, gsrc);
        }
        asm volatile("cp.async.commit_group;" ::: "memory");
    };

    issue(0, 0);
    for (int ch = 0; ch < nch; ch++) {
        const int st = ch & 1;
        if (ch + 1 < nch) {
            issue(ch + 1, st ^ 1);
            asm volatile("cp.async.wait_group 1;" ::: "memory");
        } else {
            asm volatile("cp.async.wait_group 0;" ::: "memory");
        }
        __syncthreads();
        const __nv_bfloat16* Ah = smb + (st*NB + 0)*BUF_E;
        const __nv_bfloat16* Al = smb + (st*NB + 1)*BUF_E;
        const __nv_bfloat16* Bh = smb + (st*NB + 2)*BUF_E;
        const __nv_bfloat16* Bl = smb + (st*NB + 3)*BUF_E;
#pragma unroll
        for (int kk = 0; kk < 32; kk += 16) {
            const int kcol = kk + tq*2;
            uint32_t bh[4][2], bl[4][2];
#pragma unroll
            for (int nt = 0; nt < 4; nt++) {
                int nrow = wc*32 + nt*8 + g;
                bh[nt][0] = *reinterpret_cast<const uint32_t*>(&Bh[nrow*AST + kcol]);
                bh[nt][1] = *reinterpret_cast<const uint32_t*>(&Bh[nrow*AST + kcol + 8]);
                bl[nt][0] = *reinterpret_cast<const uint32_t*>(&Bl[nrow*AST + kcol]);
                bl[nt][1] = *reinterpret_cast<const uint32_t*>(&Bl[nrow*AST + kcol + 8]);
            }
#pragma unroll
            for (int mt = 0; mt < 4; mt++) {
                int mrow = wr*64 + mt*16 + g;
                uint32_t ah[4], al[4];
                ah[0] = *reinterpret_cast<const uint32_t*>(&Ah[mrow*AST + kcol]);
                ah[1] = *reinterpret_cast<const uint32_t*>(&Ah[(mrow+8)*AST + kcol]);
                ah[2] = *reinterpret_cast<const uint32_t*>(&Ah[mrow*AST + kcol + 8]);
                ah[3] = *reinterpret_cast<const uint32_t*>(&Ah[(mrow+8)*AST + kcol + 8]);
                al[0] = *reinterpret_cast<const uint32_t*>(&Al[mrow*AST + kcol]);
                al[1] = *reinterpret_cast<const uint32_t*>(&Al[(mrow+8)*AST + kcol]);
                al[2] = *reinterpret_cast<const uint32_t*>(&Al[mrow*AST + kcol + 8]);
                al[3] = *reinterpret_cast<const uint32_t*>(&Al[(mrow+8)*AST + kcol + 8]);
#pragma unroll
                for (int nt = 0; nt < 4; nt++) {
                    mma16816(acc[mt][nt], ah, bh[nt]);
                    mma16816(acc[mt][nt], ah, bl[nt]);
                    mma16816(acc[mt][nt], al, bh[nt]);
                }
            }
        }
        __syncthreads();
    }

#pragma unroll
    for (int mt = 0; mt < 4; mt++) {
        int row = m0 + wr*64 + mt*16 + g;
#pragma unroll
        for (int nt = 0; nt < 4; nt++) {
            int col = n0 + wc*32 + nt*8 + tq*2;
            if (col < N) {
                *reinterpret_cast<float2*>(&C[(size_t)row*ldc + col]) =
                    make_float2(acc[mt][nt][0], acc[mt][nt][1]);
                *reinterpret_cast<float2*>(&C[(size_t)(row+8)*ldc + col]) =
                    make_float2(acc[mt][nt][2], acc[mt][nt][3]);
            }
        }
    }
}

// ------------------------------ rmsnorm ------------------------------------
__global__ void rmsnorm_kernel(float* __restrict__ x, const float* __restrict__ w,
                               int dim, int stride)
{
    const int row = blockIdx.x;
    float* xr = x + (size_t)row * stride;
    float ss = 0.f;
    for (int d = threadIdx.x; d < dim; d += blockDim.x) { float v = xr[d]; ss += v*v; }
    __shared__ float red[8];
#pragma unroll
    for (int o = 16; o > 0; o >>= 1) ss += __shfl_xor_sync(0xffffffffu, ss, o);
    if ((threadIdx.x & 31) == 0) red[threadIdx.x >> 5] = ss;
    __syncthreads();
    if (threadIdx.x == 0) {
        float v = 0.f;
        for (int i = 0; i < (int)(blockDim.x >> 5); i++) v += red[i];
        red[0] = v;
    }
    __syncthreads();
    const float scale = rsqrtf(red[0] / (float)dim + 1e-6f);
    for (int d = threadIdx.x; d < dim; d += blockDim.x) xr[d] = xr[d] * scale * w[d];
}

// ------------------------------ RoPE kernels -------------------------------
__global__ void rope_q_kernel(float* __restrict__ q, const float* __restrict__ cs,
                              const float* __restrict__ sn)
{
    int idx = blockIdx.x * blockDim.x + threadIdx.x;
    if (idx >= S_ * H_ * 32) return;
    int d = idx & 31, h = (idx >> 5) & 15, s = idx >> 9;
    float c = cs[s*32 + d], si = sn[s*32 + d];
    float* p = q + (size_t)s*3072 + h*192 + 128 + 2*d;
    float xr = p[0], xi = p[1];
    p[0] = xr*c - xi*si;
    p[1] = xr*si + xi*c;
}

__global__ void rope_k_kernel(const float* __restrict__ kv, float* __restrict__ kr,
                              const float* __restrict__ cs, const float* __restrict__ sn)
{
    int idx = blockIdx.x * blockDim.x + threadIdx.x;
    if (idx >= S_ * 32) return;
    int d = idx & 31, s = idx >> 5;
    float c = cs[s*32 + d], si = sn[s*32 + d];
    const float* p = kv + (size_t)s*576 + 512 + 2*d;
    float xr = p[0], xi = p[1];
    kr[(size_t)s*64 + 2*d]     = xr*c - xi*si;
    kr[(size_t)s*64 + 2*d + 1] = xr*si + xi*c;
}

// rows [s_off, s_off + nrows)
__global__ void rope_qi_kernel(float* __restrict__ qi, const float* __restrict__ cs,
                               const float* __restrict__ sn, int s_off)
{
    int idx = blockIdx.x * blockDim.x + threadIdx.x;
    int d = idx & 31, n = (idx >> 5) & 15, s = s_off + (idx >> 9);
    if (s >= S_) return;
    float c = cs[s*32 + d], si = sn[s*32 + d];
    float* p = qi + (size_t)s*2048 + n*128;
    float xr = p[d], xi = p[32 + d];
    p[d]      = xr*c - xi*si;
    p[32 + d] = xr*si + xi*c;
}

__global__ void ki_lnrope_kernel(const float* __restrict__ comb, float* __restrict__ ki,
                                 float* __restrict__ wts,
                                 const float* __restrict__ w, const float* __restrict__ b,
                                 const float* __restrict__ cs, const float* __restrict__ sn)
{
    const int s = blockIdx.x, t = threadIdx.x;
    const float* rowc = comb + (size_t)s*144;
    float* rowo = ki + (size_t)s*128;
    if (t < 16) wts[(size_t)s*16 + t] = rowc[128 + t];
    __shared__ float sh[128];
    __shared__ float warpred[4];
    __shared__ float s_mu, s_rstd;
    float v = rowc[t];
    float x = v;
#pragma unroll
    for (int o = 16; o > 0; o >>= 1) x += __shfl_xor_sync(0xffffffffu, x, o);
    if ((t & 31) == 0) warpred[t >> 5] = x;
    __syncthreads();
    if (t == 0) s_mu = (warpred[0]+warpred[1]+warpred[2]+warpred[3]) * (1.f/128.f);
    __syncthreads();
    float mu = s_mu;
    float dv = v - mu;
    float y = dv*dv;
#pragma unroll
    for (int o = 16; o > 0; o >>= 1) y += __shfl_xor_sync(0xffffffffu, y, o);
    if ((t & 31) == 0) warpred[t >> 5] = y;
    __syncthreads();
    if (t == 0) s_rstd = rsqrtf((warpred[0]+warpred[1]+warpred[2]+warpred[3]) * (1.f/128.f) + 1e-5f);
    __syncthreads();
    float nv = dv * s_rstd * w[t] + b[t];
    sh[t] = nv;
    __syncthreads();
    float outv;
    if (t < 32) {
        float c = cs[s*32 + t], si = sn[s*32 + t];
        outv = sh[t]*c - sh[t+32]*si;
    } else if (t < 64) {
        int d = t - 32;
        float c = cs[s*32 + d], si = sn[s*32 + d];
        outv = sh[d]*si + sh[t]*c;
    } else outv = nv;
    rowo[t] = outv;
}

// --------------------------- indexer scores --------------------------------
__global__ void __launch_bounds__(256) indexer_kernel(
    const float* __restrict__ qi, const float* __restrict__ ki,
    const float* __restrict__ wts, float* __restrict__ isc, int q_off)
{
    const int k0 = blockIdx.x * 64;
    const int q0 = q_off + blockIdx.y * 32;
    if (k0 > q0 + 31) return;
    extern __shared__ float ism[];
    float* kis = ism;
    float* qis = ism + 64*132;
    const int tid = threadIdx.x;
    const int ql = tid & 15;
    const int kg = tid >> 4;

#pragma unroll
    for (int e = tid; e < 64*32; e += 256) {
        int r = e >> 5, d4 = e & 31;
        *reinterpret_cast<float4*>(&kis[r*132 + d4*4]) =
            *reinterpret_cast<const float4*>(&ki[(size_t)(k0+r)*128 + d4*4]);
    }
    float acc[2][4];
#pragma unroll
    for (int r = 0; r < 2; r++)
#pragma unroll
        for (int j = 0; j < 4; j++) acc[r][j] = 0.f;

    for (int n = 0; n < 16; n++) {
        __syncthreads();
#pragma unroll
        for (int e = tid; e < 32*32; e += 256) {
            int r = e >> 5, d4 = e & 31;
            *reinterpret_cast<float4*>(&qis[r*132 + d4*4]) =
                *reinterpret_cast<const float4*>(&qi[(size_t)(q0+r)*2048 + n*128 + d4*4]);
        }
        __syncthreads();
        float dots[2][4];
#pragma unroll
        for (int r = 0; r < 2; r++)
#pragma unroll
            for (int j = 0; j < 4; j++) dots[r][j] = 0.f;
#pragma unroll 4
        for (int d4 = 0; d4 < 32; d4++) {
            float4 qv0 = *reinterpret_cast<const float4*>(&qis[(ql*2+0)*132 + d4*4]);
            float4 qv1 = *reinterpret_cast<const float4*>(&qis[(ql*2+1)*132 + d4*4]);
#pragma unroll
            for (int j = 0; j < 4; j++) {
                float4 kv = *reinterpret_cast<const float4*>(&kis[(kg*4+j)*132 + d4*4]);
                dots[0][j] += qv0.x*kv.x + qv0.y*kv.y + qv0.z*kv.z + qv0.w*kv.w;
                dots[1][j] += qv1.x*kv.x + qv1.y*kv.y + qv1.z*kv.z + qv1.w*kv.w;
            }
        }
        float w0 = wts[(size_t)(q0+ql*2+0)*16 + n] * 0.25f;
        float w1 = wts[(size_t)(q0+ql*2+1)*16 + n] * 0.25f;
#pragma unroll
        for (int j = 0; j < 4; j++) {
            acc[0][j] += fmaxf(dots[0][j] * 0.08838834764831845f, 0.f) * w0;
            acc[1][j] += fmaxf(dots[1][j] * 0.08838834764831845f, 0.f) * w1;
        }
    }
#pragma unroll
    for (int r = 0; r < 2; r++) {
        int q = q0 + ql*2 + r;
#pragma unroll
        for (int j = 0; j < 4; j++) {
            int k = k0 + kg*4 + j;
            isc[(size_t)q*2048 + k] = (k <= q) ? acc[r][j] : -1e30f;
        }
    }
}

// ------------------------------ top-k mask ----------------------------------
__global__ void __launch_bounds__(256) topk_kernel(
    const float* __restrict__ isc, unsigned char* __restrict__ mask, int q_base)
{
    const int q = q_base + blockIdx.x;
    const int n = q + 1;
    const int tid = threadIdx.x;
    unsigned char* mrow = mask + (size_t)q * 2048;
    if (n <= TOPK_) {
        for (int k = tid; k < 2048; k += 256) mrow[k] = (k <= q) ? 1 : 0;
        return;
    }
    __shared__ unsigned int keys[2048];
    __shared__ unsigned int hist[256];
    __shared__ unsigned int suf[2][256];
    __shared__ int s_d;
    __shared__ int s_cnt, s_eq;
    const float* row = isc + (size_t)q * 2048;
    for (int k = tid; k < n; k += 256) {
        unsigned int bb = __float_as_uint(row[k]);
        keys[k] = (bb & 0x80000000u) ? ~bb : (bb | 0x80000000u);
    }
    __syncthreads();

    unsigned int prefix = 0;
    int kth = TOPK_;
#pragma unroll
    for (int pass = 0; pass < 4; pass++) {
        const int shift = 24 - pass*8;
        const unsigned int hm = (pass == 0) ? 0u : (~0u << (shift + 8));
        hist[tid] = 0;
        __syncthreads();
        for (int k = tid; k < n; k += 256) {
            unsigned int key = keys[k];
            if ((key & hm) == prefix) atomicAdd(&hist[(key >> shift) & 255], 1u);
        }
        __syncthreads();
        suf[0][tid] = hist[tid];
        __syncthreads();
        int sb = 0;
#pragma unroll
        for (int off = 1; off < 256; off <<= 1) {
            unsigned int v = suf[sb][tid] + ((tid + off < 256) ? suf[sb][tid + off] : 0u);
            suf[sb ^ 1][tid] = v;
            __syncthreads();
            sb ^= 1;
        }
        const unsigned int* Ssum = suf[sb];
        if (Ssum[tid] >= (unsigned int)kth &&
            (tid == 255 || Ssum[tid + 1] < (unsigned int)kth)) s_d = tid;
        __syncthreads();
        const int d = s_d;
        const int cnt_gt = (d == 255) ? 0 : (int)Ssum[d + 1];
        kth -= cnt_gt;
        prefix |= ((unsigned int)d) << shift;
        __syncthreads();
    }

    const unsigned int T = prefix;
    if (tid == 0) { s_cnt = 0; s_eq = 0; }
    __syncthreads();
    int cg = 0, ce = 0;
    for (int k = tid; k < n; k += 256) {
        unsigned int key = keys[k];
        if (key > T) cg++;
        else if (key == T) ce++;
    }
#pragma unroll
    for (int o = 16; o > 0; o >>= 1) {
        cg += __shfl_xor_sync(0xffffffffu, cg, o);
        ce += __shfl_xor_sync(0xffffffffu, ce, o);
    }
    if ((tid & 31) == 0) { atomicAdd(&s_cnt, cg); atomicAdd(&s_eq, ce); }
    __syncthreads();
    const int ngt = s_cnt, neq = s_eq;
    const int take_eq = TOPK_ - ngt;
    if (take_eq >= neq) {
        for (int k = tid; k < 2048; k += 256)
            mrow[k] = (k < n && keys[k] >= T) ? 1 : 0;
    } else {
        for (int k = tid; k < 2048; k += 256)
            mrow[k] = (k < n && keys[k] > T) ? 1 : 0;
        __syncthreads();
        if (tid == 0) {
            int c = 0;
            for (int k = 0; k < n && c < take_eq; k++)
                if (keys[k] == T) { mrow[k] = 1; c++; }
        }
    }
}

// --------------------------- flash attention (FFMA2) ------------------------
#define FL_QN 132
#define FL_QR 68
__global__ void __launch_bounds__(256) flash_kernel(
    const float* __restrict__ qb, const float* __restrict__ kvb,
    const float* __restrict__ krope, const unsigned char* __restrict__ msk,
    float* __restrict__ attn, int q_base)
{
    const int h  = blockIdx.y;
    const int q0 = q_base + (gridDim.x - 1 - blockIdx.x) * 64;
    extern __shared__ float smf[];
    float* qn = smf;
    float* qr = qn + 64*FL_QN;
    float* kn = qr + 64*FL_QR;
    float* kr = kn + 32*FL_QN;
    float* vs = kr + 32*FL_QR;
    float* pr = vs + 32*FL_QN;
    unsigned int* um = (unsigned int*)(pr + 64*33);

    const int tid = threadIdx.x;
    const int ql = tid >> 2;
    const int t  = tid & 3;

#pragma unroll
    for (int e = tid; e < 64*32; e += 256) {
        int r = e >> 5, d4 = e & 31;
        *reinterpret_cast<float4*>(&qn[r*FL_QN + d4*4]) =
            *reinterpret_cast<const float4*>(&qb[(size_t)(q0+r)*3072 + h*192 + d4*4]);
    }
#pragma unroll
    for (int e = tid; e < 64*16; e += 256) {
        int r = e >> 4, d4 = e & 15;
        *reinterpret_cast<float4*>(&qr[r*FL_QR + d4*4]) =
            *reinterpret_cast<const float4*>(&qb[(size_t)(q0+r)*3072 + h*192 + 128 + d4*4]);
    }

    float m = -INFINITY, l = 0.f;
    unsigned long long o2[16];
#pragma unroll
    for (int i = 0; i < 16; i++) o2[i] = 0ull;

    const int kend = q0 + 64;
    for (int k0 = 0; k0 < kend; k0 += 32) {
        __syncthreads();
#pragma unroll
        for (int e = tid; e < 32*32; e += 256) {
            int r = e >> 5, d4 = e & 31;
            *reinterpret_cast<float4*>(&kn[r*FL_QN + d4*4]) =
                *reinterpret_cast<const float4*>(&kvb[(size_t)(k0+r)*4096 + h*256 + d4*4]);
            *reinterpret_cast<float4*>(&vs[r*FL_QN + d4*4]) =
                *reinterpret_cast<const float4*>(&kvb[(size_t)(k0+r)*4096 + h*256 + 128 + d4*4]);
        }
#pragma unroll
        for (int e = tid; e < 32*16; e += 256) {
            int r = e >> 4, d4 = e & 15;
            *reinterpret_cast<float4*>(&kr[r*FL_QR + d4*4]) =
                *reinterpret_cast<const float4*>(&krope[(size_t)(k0+r)*64 + d4*4]);
        }
#pragma unroll
        for (int e = tid; e < 512; e += 256) {
            int r = e >> 3, c = e & 7;
            um[r*8 + c] = *reinterpret_cast<const unsigned int*>(
                &msk[(size_t)(q0+r)*2048 + k0 + c*4]);
        }
        __syncthreads();

        unsigned long long s2[8];
#pragma unroll
        for (int j = 0; j < 8; j++) s2[j] = 0ull;
#pragma unroll 4
        for (int d4 = 0; d4 < 32; d4++) {
            float4 qv = *reinterpret_cast<const float4*>(&qn[ql*FL_QN + d4*4]);
            unsigned long long qa = packf2(qv.x, qv.y), qc = packf2(qv.z, qv.w);
#pragma unroll
            for (int j = 0; j < 8; j++) {
                float4 kv = *reinterpret_cast<const float4*>(&kn[(j*4+t)*FL_QN + d4*4]);
                ffma2(s2[j], qa, packf2(kv.x, kv.y));
                ffma2(s2[j], qc, packf2(kv.z, kv.w));
            }
        }
#pragma unroll 4
        for (int d4 = 0; d4 < 16; d4++) {
            float4 qv = *reinterpret_cast<const float4*>(&qr[ql*FL_QR + d4*4]);
            unsigned long long qa = packf2(qv.x, qv.y), qc = packf2(qv.z, qv.w);
#pragma unroll
            for (int j = 0; j < 8; j++) {
                float4 kv = *reinterpret_cast<const float4*>(&kr[(j*4+t)*FL_QR + d4*4]);
                ffma2(s2[j], qa, packf2(kv.x, kv.y));
                ffma2(s2[j], qc, packf2(kv.z, kv.w));
            }
        }
        float s[8];
#pragma unroll
        for (int j = 0; j < 8; j++) {
            float lo, hi;
            unpackf2(s2[j], lo, hi);
            s[j] = lo + hi;
        }
        const int qg = q0 + ql;
        const unsigned char* umb = (const unsigned char*)um;
#pragma unroll
        for (int j = 0; j < 8; j++) {
            int kl = j*4 + t;
            bool ok = (k0 + kl <= qg) && umb[ql*32 + kl];
            s[j] = ok ? s[j] * 0.07216878364870323f : -INFINITY;
        }
        float mt = s[0];
#pragma unroll
        for (int j = 1; j < 8; j++) mt = fmaxf(mt, s[j]);
        mt = fmaxf(mt, __shfl_xor_sync(0xffffffffu, mt, 1));
        mt = fmaxf(mt, __shfl_xor_sync(0xffffffffu, mt, 2));
        float mn  = fmaxf(m, mt);
        float mns = (mn > -INFINITY) ? mn : 0.f;
        float alpha = (m > -INFINITY) ? __expf(m - mns) : 0.f;
        float ls = 0.f;
#pragma unroll
        for (int j = 0; j < 8; j++) {
            float p = (s[j] > -INFINITY) ? __expf(s[j] - mns) : 0.f;
            pr[ql*33 + j*4 + t] = p;
            ls += p;
        }
        ls += __shfl_xor_sync(0xffffffffu, ls, 1);
        ls += __shfl_xor_sync(0xffffffffu, ls, 2);
        l = l * alpha + ls;
        m = mn;
        unsigned long long al2 = packf2(alpha, alpha);
#pragma unroll
        for (int i = 0; i < 16; i++) mulf2(o2[i], al2);
        __syncwarp();
#pragma unroll 4
        for (int kk = 0; kk < 32; kk++) {
            float p = pr[ql*33 + kk];
            unsigned long long pp = packf2(p, p);
#pragma unroll
            for (int g = 0; g < 8; g++) {
                float4 v4 = *reinterpret_cast<const float4*>(&vs[kk*FL_QN + g*16 + t*4]);
                ffma2(o2[g*2],     pp, packf2(v4.x, v4.y));
                ffma2(o2[g*2 + 1], pp, packf2(v4.z, v4.w));
            }
        }
    }
    const float inv = 1.f / l;
#pragma unroll
    for (int g = 0; g < 8; g++) {
        float o0, o1, o2v, o3;
        unpackf2(o2[g*2],     o0, o1);
        unpackf2(o2[g*2 + 1], o2v, o3);
        float* dst = &attn[(size_t)(q0+ql)*2048 + h*128 + g*16 + t*4];
        dst[0] = o0 * inv; dst[1] = o1 * inv;
        dst[2] = o2v * inv; dst[3] = o3 * inv;
    }
}

// ------------------------------ launch -------------------------------------
extern "C" void kernel_launch(void* const* d_in, const int* in_sizes, int n_in,
                              void* d_out, int out_size)
{
    const float* hidden     = (const float*)d_in[0];
    const float* cosb       = (const float*)d_in[1];
    const float* sinb       = (const float*)d_in[2];
    const float* w_q_a      = (const float*)d_in[3];
    const float* q_a_ln_w   = (const float*)d_in[4];
    const float* w_q_b      = (const float*)d_in[5];
    const float* w_kv_a     = (const float*)d_in[6];
    const float* kv_a_ln_w  = (const float*)d_in[7];
    const float* w_kv_b     = (const float*)d_in[8];
    const float* w_o        = (const float*)d_in[9];
    const float* idx_wq_b   = (const float*)d_in[10];
    const float* idx_wk     = (const float*)d_in[11];
    const float* idx_k_ln_w = (const float*)d_in[12];
    const float* idx_k_ln_b = (const float*)d_in[13];
    const float* idx_w_proj = (const float*)d_in[14];
    float* out = (float*)d_out;

    float *cq, *qbp, *kv, *krope, *kvb, *qi, *ki, *wts, *isc, *attn, *wcomb, *kicomb;
    unsigned char* msk;
    cudaGetSymbolAddress((void**)&cq,    g_cq);
    cudaGetSymbolAddress((void**)&qbp,   g_q);
    cudaGetSymbolAddress((void**)&kv,    g_kv);
    cudaGetSymbolAddress((void**)&krope, g_krope);
    cudaGetSymbolAddress((void**)&kvb,   g_kvb);
    cudaGetSymbolAddress((void**)&qi,    g_qi);
    cudaGetSymbolAddress((void**)&ki,    g_ki);
    cudaGetSymbolAddress((void**)&wts,   g_wts);
    cudaGetSymbolAddress((void**)&isc,   g_isc);
    cudaGetSymbolAddress((void**)&msk,   g_mask);
    cudaGetSymbolAddress((void**)&attn,  g_attn);
    cudaGetSymbolAddress((void**)&wcomb, g_wcomb);
    cudaGetSymbolAddress((void**)&kicomb,g_kicomb);

    __nv_bfloat16 *H0,*H1,*CQ0,*CQ1,*KV0,*KV1,*AT0,*AT1;
    __nv_bfloat16 *Wkva0,*Wkva1,*Wqb0,*Wqb1,*Wkvb0,*Wkvb1,*Wo0,*Wo1;
    cudaGetSymbolAddress((void**)&H0,  g_H0);   cudaGetSymbolAddress((void**)&H1,  g_H1);
    cudaGetSymbolAddress((void**)&CQ0, g_CQ0);  cudaGetSymbolAddress((void**)&CQ1, g_CQ1);
    cudaGetSymbolAddress((void**)&KV0, g_KV0);  cudaGetSymbolAddress((void**)&KV1, g_KV1);
    cudaGetSymbolAddress((void**)&AT0, g_AT0);  cudaGetSymbolAddress((void**)&AT1, g_AT1);
    cudaGetSymbolAddress((void**)&Wkva0,g_Wkva0); cudaGetSymbolAddress((void**)&Wkva1,g_Wkva1);
    cudaGetSymbolAddress((void**)&Wqb0, g_Wqb0); cudaGetSymbolAddress((void**)&Wqb1, g_Wqb1);
    cudaGetSymbolAddress((void**)&Wkvb0,g_Wkvb0); cudaGetSymbolAddress((void**)&Wkvb1,g_Wkvb1);
    cudaGetSymbolAddress((void**)&Wo0,  g_Wo0);  cudaGetSymbolAddress((void**)&Wo1,  g_Wo1);

    const int GSM2 = 8 * BUF_E * 2;        // 81920 B
    const int GSMF = 2 * F_STG * 4;        // 36864 B
    const int ISM  = (64 + 32) * 132 * 4;  // 50688 B
    cudaFuncSetAttribute(gemm_mma2, cudaFuncAttributeMaxDynamicSharedMemorySize, GSM2);
    cudaFuncSetAttribute(gemm_f32,  cudaFuncAttributeMaxDynamicSharedMemorySize, GSMF);
    cudaFuncSetAttribute(indexer_kernel, cudaFuncAttributeMaxDynamicSharedMemorySize, ISM);

    const dim3 blk(256);
    const dim3 tb(32, 8);
    cudaStream_t s1 = g_si.s1, s2 = g_si.s2;

    // ---- fork ----
    cudaEventRecord(g_si.ev0, 0);
    cudaStreamWaitEvent(s1, g_si.ev0, 0);
    cudaStreamWaitEvent(s2, g_si.ev0, 0);

    // ======== s2: ki/wts chain (independent of cq) ========
    pack_wik<<<(4096*144 + 255)/256, 256, 0, s2>>>(idx_wk, idx_w_proj, wcomb);
    gemm_f32_m32<<<dim3(2, 64), blk, 0, s2>>>(hidden, wcomb, kicomb, 2048, 144, 4096, 4096, 144);
    ki_lnrope_kernel<<<2048, 128, 0, s2>>>(kicomb, ki, wts, idx_k_ln_w, idx_k_ln_b, cosb, sinb);
    cudaEventRecord(g_si.ev_ki, s2);

    // ======== default: cq -> qi-high -> indexer-high -> topk-high (bit-exact) ==
    gemm_f32<<<dim3(12, 16), blk, GSMF>>>(hidden, w_q_a, cq, 2048, 1536, 4096, 4096, 0);
    rmsnorm_kernel<<<2048, 256>>>(cq, q_a_ln_w, 1536, 1536);
    cudaEventRecord(g_si.ev_cq, 0);
    gemm_f32<<<dim3(16, 12), blk, GSMF>>>(cq, idx_wq_b, qi, 2048, 2048, 1536, 1536, 512);
    cudaEventRecord(g_si.ev_qih, 0);
    rope_qi_kernel<<<(1536*16*32)/256, 256>>>(qi, cosb, sinb, 512);
    cudaStreamWaitEvent(0, g_si.ev_ki, 0);
    indexer_kernel<<<dim3(32, 48), blk, ISM>>>(qi, ki, wts, isc, 512);
    topk_kernel<<<1536, 256>>>(isc, msk, 512);

    // ======== s1: value path (overlaps indexer chain) ========
    act_conv<<<(2048*2048+255)/256, 256, 0, s1>>>(hidden, H0, H1, 2048, 2048, 4096);
    wconv_t<<<dim3(640/32,  4096/32), tb, 0, s1>>>(w_kv_a, Wkva0, Wkva1, 4096, 576);
    wconv_t<<<dim3(3072/32, 1536/32), tb, 0, s1>>>(w_q_b,  Wqb0,  Wqb1,  1536, 3072);
    wconv_t<<<dim3(4096/32, 512/32),  tb, 0, s1>>>(w_kv_b, Wkvb0, Wkvb1, 512,  4096);
    wconv_t<<<dim3(4096/32, 2048/32), tb, 0, s1>>>(w_o,    Wo0,   Wo1,   2048, 4096);
    gemm_mma2<<<dim3(5, 16), blk, GSM2, s1>>>(H0, H1, Wkva0, Wkva1, kv, 576, 4096, 576);
    rope_k_kernel<<<(2048*32)/256, 256, 0, s1>>>(kv, krope, cosb, sinb);
    rmsnorm_kernel<<<2048, 256, 0, s1>>>(kv, kv_a_ln_w, 512, 576);
    act_conv<<<(2048*256+255)/256, 256, 0, s1>>>(kv, KV0, KV1, 2048, 256, 576);
    gemm_mma2<<<dim3(32, 16), blk, GSM2, s1>>>(KV0, KV1, Wkvb0, Wkvb1, kvb, 4096, 512, 4096);
    cudaStreamWaitEvent(s1, g_si.ev_cq, 0);
    act_conv<<<(2048*768+255)/256, 256, 0, s1>>>(cq, CQ0, CQ1, 2048, 768, 1536);
    gemm_mma2<<<dim3(24, 16), blk, GSM2, s1>>>(CQ0, CQ1, Wqb0, Wqb1, qbp, 3072, 1536, 3072);
    rope_q_kernel<<<(2048*16*32)/256, 256, 0, s1>>>(qbp, cosb, sinb);
    cudaEventRecord(g_si.ev_val, s1);

    // ======== s2: low-q chain (overlaps topk-high + flashA) ========
    cudaStreamWaitEvent(s2, g_si.ev_cq, 0);
    cudaStreamWaitEvent(s2, g_si.ev_qih, 0);
    gemm_f32<<<dim3(16, 4), blk, GSMF, s2>>>(cq, idx_wq_b, qi, 2048, 2048, 1536, 1536, 0);
    rope_qi_kernel<<<(512*16*32)/256, 256, 0, s2>>>(qi, cosb, sinb, 0);
    indexer_kernel<<<dim3(8, 16), blk, ISM, s2>>>(qi, ki, wts, isc, 0);
    topk_kernel<<<512, 256, 0, s2>>>(isc, msk, 0);
    cudaEventRecord(g_si.ev_tkB, s2);

    // ---- flashA (q >= 512) on default after topk-high + value path ----
    cudaStreamWaitEvent(0, g_si.ev_val, 0);
    const int FLASH_SMEM = (64*FL_QN + 64*FL_QR + 32*FL_QN + 32*FL_QR + 32*FL_QN + 64*33)*4
                           + 64*32;
    cudaFuncSetAttribute(flash_kernel, cudaFuncAttributeMaxDynamicSharedMemorySize, FLASH_SMEM);
    flash_kernel<<<dim3(24, 16), blk, FLASH_SMEM>>>(qbp, kvb, krope, msk, attn, 512);

    // flashB (q < 512) on s1 after its mask is ready
    cudaStreamWaitEvent(s1, g_si.ev_tkB, 0);
    flash_kernel<<<dim3(8, 16), blk, FLASH_SMEM, s1>>>(qbp, kvb, krope, msk, attn, 0);
    cudaEventRecord(g_si.ev_fb, s1);

    // default: w_o high (rows 512..2047) right after flashA, overlapping flashB
    act_conv<<<(1536*1024+255)/256, 256>>>(attn + (size_t)512*2048,
                                           AT0 + (size_t)512*2048,
                                           AT1 + (size_t)512*2048, 1536, 1024, 2048);
    gemm_mma2<<<dim3(32, 12), blk, GSM2>>>(AT0 + (size_t)512*2048, AT1 + (size_t)512*2048,
                                           Wo0, Wo1, out + (size_t)512*4096,
                                           4096, 2048, 4096);

    // default: w_o low (rows 0..511) after flashB
    cudaStreamWaitEvent(0, g_si.ev_fb, 0);
    act_conv<<<(512*1024+255)/256, 256>>>(attn, AT0, AT1, 512, 1024, 2048);
    gemm_mma2<<<dim3(32, 4), blk, GSM2>>>(AT0, AT1, Wo0, Wo1, out, 4096, 2048, 4096);
}

// round 17
// speedup vs baseline: 1.0267x; 1.0267x over previous
#include <cuda_runtime.h>
#include <cuda_bf16.h>
#include <math.h>
#include <stdint.h>

// ---------------------------------------------------------------------------
// DeepSeek V3.2 sparse attention, B=1 S=2048 D=4096 H=16 DN=128 DR=64 DV=128
// Indexer chain: fp32 (FFMA2) GEMMs + fp32 indexer — per-output accumulation
//   order bit-identical to all passing rounds -> deterministic top-k mask.
// Value path: mma.sync bf16 2-term split; flash FFMA2 (mask-independent).
// R17: R15 structure + (a) flashB runs on s1 CONCURRENT with flashA,
//   (b) indexer/topk split by q-range (qi GEMM kept whole — R16's split of the
//   GEMM was the regression). Low chain (6% of indexer, trivial topk) on s2.
// ---------------------------------------------------------------------------

#define S_ 2048
#define H_ 16
#define TOPK_ 1024

// ------------------------- fp32 scratch ------------------------------------
__device__ float g_cq   [S_ * 1536];
__device__ float g_q    [S_ * 3072];
__device__ float g_kv   [S_ * 576];
__device__ float g_krope[S_ * 64];
__device__ float g_kvb  [S_ * 4096];
__device__ float g_qi   [S_ * 2048];
__device__ float g_ki   [S_ * 128];
__device__ float g_wts  [S_ * 16];
__device__ float g_isc  [S_ * S_];
__device__ unsigned char g_mask[S_ * S_];
__device__ float g_attn [S_ * 2048];
__device__ float g_wcomb [4096 * 144];
__device__ float g_kicomb[S_ * 144];

// ------------------------- bf16 2-term split buffers ------------------------
__device__ __nv_bfloat16 g_H0 [2048*4096], g_H1 [2048*4096];
__device__ __nv_bfloat16 g_CQ0[2048*1536], g_CQ1[2048*1536];
__device__ __nv_bfloat16 g_KV0[2048*512],  g_KV1[2048*512];
__device__ __nv_bfloat16 g_AT0[2048*2048], g_AT1[2048*2048];
__device__ __nv_bfloat16 g_Wkva0[640*4096], g_Wkva1[640*4096];
__device__ __nv_bfloat16 g_Wqb0[3072*1536], g_Wqb1[3072*1536];
__device__ __nv_bfloat16 g_Wkvb0[4096*512], g_Wkvb1[4096*512];
__device__ __nv_bfloat16 g_Wo0 [4096*2048], g_Wo1 [4096*2048];

// ------------------------- streams / events (global ctor) -------------------
namespace {
struct SInit {
    cudaStream_t s1 = nullptr, s2 = nullptr;
    cudaEvent_t ev0 = nullptr, ev_cq = nullptr, ev_val = nullptr, ev_ki = nullptr;
    cudaEvent_t ev_qi = nullptr, ev_tkB = nullptr, ev_fb = nullptr, ev_woB = nullptr;
    SInit() {
        cudaStreamCreateWithFlags(&s1, cudaStreamNonBlocking);
        cudaStreamCreateWithFlags(&s2, cudaStreamNonBlocking);
        cudaEventCreateWithFlags(&ev0,    cudaEventDisableTiming);
        cudaEventCreateWithFlags(&ev_cq,  cudaEventDisableTiming);
        cudaEventCreateWithFlags(&ev_val, cudaEventDisableTiming);
        cudaEventCreateWithFlags(&ev_ki,  cudaEventDisableTiming);
        cudaEventCreateWithFlags(&ev_qi,  cudaEventDisableTiming);
        cudaEventCreateWithFlags(&ev_tkB, cudaEventDisableTiming);
        cudaEventCreateWithFlags(&ev_fb,  cudaEventDisableTiming);
        cudaEventCreateWithFlags(&ev_woB, cudaEventDisableTiming);
    }
};
SInit g_si;
}

// ------------------------- PTX helpers -------------------------------------
__device__ __forceinline__ uint32_t smem_u32(const void* p) {
    uint32_t a;
    asm("{ .reg .u64 t; cvta.to.shared.u64 t, %1; cvt.u32.u64 %0, t; }" : "=r"(a) : "l"(p));
    return a;
}
__device__ __forceinline__ void cp16(uint32_t dst, const void* src) {
    asm volatile("cp.async.cg.shared.global [%0], [%1], 16;" :: "r"(dst), "l"(src));
}
__device__ __forceinline__ void cp16z(uint32_t dst, const void* src) {
    asm volatile("cp.async.cg.shared.global [%0], [%1], 16, 0;" :: "r"(dst), "l"(src));
}
__device__ __forceinline__ void mma16816(float* d, const uint32_t* a, const uint32_t* b) {
    asm volatile("mma.sync.aligned.m16n8k16.row.col.f32.bf16.bf16.f32 "
        "{%0,%1,%2,%3}, {%4,%5,%6,%7}, {%8,%9}, {%0,%1,%2,%3};"
        : "+f"(d[0]), "+f"(d[1]), "+f"(d[2]), "+f"(d[3])
        : "r"(a[0]), "r"(a[1]), "r"(a[2]), "r"(a[3]), "r"(b[0]), "r"(b[1]));
}
__device__ __forceinline__ unsigned long long packf2(float lo, float hi) {
    unsigned long long v;
    asm("mov.b64 %0, {%1, %2};" : "=l"(v) : "f"(lo), "f"(hi));
    return v;
}
__device__ __forceinline__ void unpackf2(unsigned long long v, float& lo, float& hi) {
    asm("mov.b64 {%0, %1}, %2;" : "=f"(lo), "=f"(hi) : "l"(v));
}
__device__ __forceinline__ void ffma2(unsigned long long& d, unsigned long long a,
                                      unsigned long long b) {
    asm("fma.rn.f32x2 %0, %1, %2, %0;" : "+l"(d) : "l"(a), "l"(b));
}
__device__ __forceinline__ void mulf2(unsigned long long& d, unsigned long long a) {
    asm("mul.rn.f32x2 %0, %0, %1;" : "+l"(d) : "l"(a));
}

// ------------------------- fp32 GEMM (FFMA2, pipelined, bit-exact) ----------
#define FST 20
#define F_ASZ (128*FST)
#define F_BSZ (16*128)
#define F_STG (F_ASZ + F_BSZ)
__global__ void __launch_bounds__(256, 2) gemm_f32(
    const float* __restrict__ A, const float* __restrict__ B,
    float* __restrict__ C, int M, int N, int K, int lda)
{
    extern __shared__ float smf[];
    const uint32_t sbase = smem_u32(smf);
    const int tid = threadIdx.x;
    const int tx = tid & 15, ty = tid >> 4;
    const int m0 = blockIdx.y * 128;
    const int n0 = blockIdx.x * 128;

    unsigned long long acc[8][4];
#pragma unroll
    for (int i = 0; i < 8; i++)
#pragma unroll
        for (int j = 0; j < 4; j++) acc[i][j] = 0ull;

    auto issue = [&](int k0, int st) {
#pragma unroll
        for (int i = 0; i < 2; i++) {
            int e = tid + i*256;
            int row = e >> 2, seg = e & 3;
            const float* src = &A[(size_t)(m0+row)*lda + k0 + seg*4];
            uint32_t dst = sbase + (uint32_t)(st*F_STG + row*FST + seg*4)*4;
            cp16(dst, src);
        }
#pragma unroll
        for (int i = 0; i < 2; i++) {
            int e = tid + i*256;
            int kk = e >> 5, n4 = e & 31;
            int col = n0 + n4*4;
            const float* src = &B[(size_t)(k0+kk)*N + col];
            uint32_t dst = sbase + (uint32_t)(st*F_STG + F_ASZ + kk*128 + n4*4)*4;
            if (col < N) cp16(dst, src);
            else         cp16z(dst, B);
        }
        asm volatile("cp.async.commit_group;" ::: "memory");
    };

    const int nch = K >> 4;
    issue(0, 0);
    for (int ch = 0; ch < nch; ch++) {
        const int st = ch & 1;
        if (ch + 1 < nch) {
            issue((ch + 1) << 4, st ^ 1);
            asm volatile("cp.async.wait_group 1;" ::: "memory");
        } else {
            asm volatile("cp.async.wait_group 0;" ::: "memory");
        }
        __syncthreads();
        const float* As = smf + st*F_STG;
        const float* Bs = smf + st*F_STG + F_ASZ;
#pragma unroll
        for (int kk2 = 0; kk2 < 16; kk2 += 2) {
            float2 a2[8];
#pragma unroll
            for (int i = 0; i < 8; i++)
                a2[i] = *reinterpret_cast<const float2*>(&As[(ty*8+i)*FST + kk2]);
#pragma unroll
            for (int u = 0; u < 2; u++) {
                const int kk = kk2 + u;
                unsigned long long ap[8], bp[4];
#pragma unroll
                for (int i = 0; i < 8; i++) {
                    float a = u ? a2[i].y : a2[i].x;
                    ap[i] = packf2(a, a);
                }
                float4 b0 = *reinterpret_cast<const float4*>(&Bs[kk*128 + tx*8]);
                float4 b1 = *reinterpret_cast<const float4*>(&Bs[kk*128 + tx*8 + 4]);
                bp[0] = packf2(b0.x, b0.y); bp[1] = packf2(b0.z, b0.w);
                bp[2] = packf2(b1.x, b1.y); bp[3] = packf2(b1.z, b1.w);
#pragma unroll
                for (int i = 0; i < 8; i++)
#pragma unroll
                    for (int j = 0; j < 4; j++) ffma2(acc[i][j], ap[i], bp[j]);
            }
        }
        __syncthreads();
    }
#pragma unroll
    for (int i = 0; i < 8; i++) {
        int row = m0 + ty*8 + i;
#pragma unroll
        for (int j = 0; j < 4; j++) {
            int col = n0 + tx*8 + j*2;
            float lo, hi;
            unpackf2(acc[i][j], lo, hi);
            *reinterpret_cast<float2*>(&C[(size_t)row*N + col]) = make_float2(lo, hi);
        }
    }
}

// ------------------ fp32 GEMM, 32-row tile (skinny N), FFMA2 ----------------
__global__ void __launch_bounds__(256, 2) gemm_f32_m32(
    const float* __restrict__ A, const float* __restrict__ B,
    float* __restrict__ C, int M, int N, int K, int lda, int ldc)
{
    __shared__ float As[2][32*FST];
    __shared__ float Bs[2][16*128];
    const int tid = threadIdx.x;
    const int tx = tid & 15, ty = tid >> 4;
    const int m0 = blockIdx.y * 32;
    const int n0 = blockIdx.x * 128;

    unsigned long long acc[2][4];
#pragma unroll
    for (int i = 0; i < 2; i++)
#pragma unroll
        for (int j = 0; j < 4; j++) acc[i][j] = 0ull;

    auto issue = [&](int k0, int st) {
        if (tid < 128) {
            int row = tid >> 2, seg = tid & 3;
            const float* src = &A[(size_t)(m0+row)*lda + k0 + seg*4];
            cp16(smem_u32(&As[st][row*FST + seg*4]), src);
        }
#pragma unroll
        for (int i = 0; i < 2; i++) {
            int e = tid + i*256;
            int kk = e >> 5, n4 = e & 31;
            int col = n0 + n4*4;
            const float* src = &B[(size_t)(k0+kk)*N + col];
            uint32_t dst = smem_u32(&Bs[st][kk*128 + n4*4]);
            if (col < N) cp16(dst, src);
            else         cp16z(dst, B);
        }
        asm volatile("cp.async.commit_group;" ::: "memory");
    };

    const int nch = K >> 4;
    issue(0, 0);
    for (int ch = 0; ch < nch; ch++) {
        const int st = ch & 1;
        if (ch + 1 < nch) {
            issue((ch + 1) << 4, st ^ 1);
            asm volatile("cp.async.wait_group 1;" ::: "memory");
        } else {
            asm volatile("cp.async.wait_group 0;" ::: "memory");
        }
        __syncthreads();
#pragma unroll
        for (int kk = 0; kk < 16; kk++) {
            float a0 = As[st][(ty*2+0)*FST + kk];
            float a1 = As[st][(ty*2+1)*FST + kk];
            unsigned long long ap0 = packf2(a0, a0), ap1 = packf2(a1, a1);
            float4 b0 = *reinterpret_cast<const float4*>(&Bs[st][kk*128 + tx*8]);
            float4 b1 = *reinterpret_cast<const float4*>(&Bs[st][kk*128 + tx*8 + 4]);
            unsigned long long bp[4] = {packf2(b0.x,b0.y), packf2(b0.z,b0.w),
                                        packf2(b1.x,b1.y), packf2(b1.z,b1.w)};
#pragma unroll
            for (int j = 0; j < 4; j++) { ffma2(acc[0][j], ap0, bp[j]); ffma2(acc[1][j], ap1, bp[j]); }
        }
        __syncthreads();
    }
#pragma unroll
    for (int i = 0; i < 2; i++) {
        int row = m0 + ty*2 + i;
#pragma unroll
        for (int j = 0; j < 4; j++) {
            int col = n0 + tx*8 + j*2;
            float lo, hi;
            unpackf2(acc[i][j], lo, hi);
            if (col < N)     C[(size_t)row*ldc + col]     = lo;
            if (col + 1 < N) C[(size_t)row*ldc + col + 1] = hi;
        }
    }
}

__global__ void pack_wik(const float* __restrict__ wk, const float* __restrict__ wp,
                         float* __restrict__ comb)
{
    int i = blockIdx.x * 256 + threadIdx.x;
    if (i >= 4096*144) return;
    int k = i / 144, c = i - k*144;
    comb[i] = (c < 128) ? wk[(size_t)k*128 + c] : wp[(size_t)k*16 + (c-128)];
}

// ------------------------- conversions -------------------------------------
__global__ void act_conv(const float* __restrict__ X, __nv_bfloat16* __restrict__ hi,
                         __nv_bfloat16* __restrict__ lo, int M, int Khalf, int lda)
{
    int i = blockIdx.x * 256 + threadIdx.x;
    if (i >= M * Khalf) return;
    int m = i / Khalf, kp = i - m * Khalf;
    float2 v = *reinterpret_cast<const float2*>(&X[(size_t)m*lda + kp*2]);
    __nv_bfloat16 h0 = __float2bfloat16(v.x), h1 = __float2bfloat16(v.y);
    __nv_bfloat16 l0 = __float2bfloat16(v.x - __bfloat162float(h0));
    __nv_bfloat16 l1 = __float2bfloat16(v.y - __bfloat162float(h1));
    size_t o = (size_t)m * (Khalf*2) + kp*2;
    *reinterpret_cast<__nv_bfloat162*>(&hi[o]) = __halves2bfloat162(h0, h1);
    *reinterpret_cast<__nv_bfloat162*>(&lo[o]) = __halves2bfloat162(l0, l1);
}

__global__ void wconv_t(const float* __restrict__ W, __nv_bfloat16* __restrict__ hi,
                        __nv_bfloat16* __restrict__ lo, int K, int N)
{
    __shared__ float t[32][33];
    int n0 = blockIdx.x*32, k0 = blockIdx.y*32;
    int tx = threadIdx.x, ty = threadIdx.y;
#pragma unroll
    for (int r = 0; r < 4; r++) {
        int k = k0 + ty + r*8, n = n0 + tx;
        t[tx][ty + r*8] = (n < N) ? W[(size_t)k*N + n] : 0.f;
    }
    __syncthreads();
#pragma unroll
    for (int r = 0; r < 4; r++) {
        int n = n0 + ty + r*8, k = k0 + tx;
        float x = t[ty + r*8][tx];
        __nv_bfloat16 h = __float2bfloat16(x);
        hi[(size_t)n*K + k] = h;
        lo[(size_t)n*K + k] = __float2bfloat16(x - __bfloat162float(h));
    }
}

// ------------------------- mma.sync 2-term GEMM ----------------------------
#define AST 40
#define BUF_E (128*AST)
__global__ void __launch_bounds__(256) gemm_mma2(
    const __nv_bfloat16* __restrict__ A0, const __nv_bfloat16* __restrict__ A1,
    const __nv_bfloat16* __restrict__ B0, const __nv_bfloat16* __restrict__ B1,
    float* __restrict__ C, int N, int K, int ldc)
{
    constexpr int NB = 4;
    extern __shared__ __nv_bfloat16 smb[];
    const uint32_t sbase = smem_u32(smb);
    const int tid = threadIdx.x;
    const int wid = tid >> 5, lane = tid & 31;
    const int wr = wid >> 2, wc = wid & 3;
    const int m0 = blockIdx.y * 128;
    const int n0 = blockIdx.x * 128;
    const int g = lane >> 2, tq = lane & 3;

    float acc[4][4][4];
#pragma unroll
    for (int mt = 0; mt < 4; mt++)
#pragma unroll
        for (int nt = 0; nt < 4; nt++)
#pragma unroll
            for (int i = 0; i < 4; i++) acc[mt][nt][i] = 0.f;

    const __nv_bfloat16* srcs[NB] = {A0, A1, B0, B1};
    const int nch = K >> 5;

    auto issue = [&](int ch, int st) {
        const int kb = ch << 5;
#pragma unroll
        for (int i = 0; i < NB*2; i++) {
            int e = tid + i*256;
            int buf = e >> 9;
            int r   = (e >> 2) & 127;
            int seg = e & 3;
            int grow = (buf < 2) ? (m0 + r) : (n0 + r);
            const __nv_bfloat16* gsrc = srcs[buf] + (size_t)grow*K + kb + seg*8;
            uint32_t daddr = sbase + (uint32_t)((st*NB + buf)*BUF_E + r*AST + seg*8)*2;
            cp16(daddr, gsrc);
        }
        asm volatile("cp.async.commit_group;" ::: "memory");
    };

    issue(0, 0);
    for (int ch = 0; ch < nch; ch++) {
        const int st = ch & 1;
        if (ch + 1 < nch) {
            issue(ch + 1, st ^ 1);
            asm volatile("cp.async.wait_group 1;" ::: "memory");
        } else {
            asm volatile("cp.async.wait_group 0;" ::: "memory");
        }
        __syncthreads();
        const __nv_bfloat16* Ah = smb + (st*NB + 0)*BUF_E;
        const __nv_bfloat16* Al = smb + (st*NB + 1)*BUF_E;
        const __nv_bfloat16* Bh = smb + (st*NB + 2)*BUF_E;
        const __nv_bfloat16* Bl = smb + (st*NB + 3)*BUF_E;
#pragma unroll
        for (int kk = 0; kk < 32; kk += 16) {
            const int kcol = kk + tq*2;
            uint32_t bh[4][2], bl[4][2];
#pragma unroll
            for (int nt = 0; nt < 4; nt++) {
                int nrow = wc*32 + nt*8 + g;
                bh[nt][0] = *reinterpret_cast<const uint32_t*>(&Bh[nrow*AST + kcol]);
                bh[nt][1] = *reinterpret_cast<const uint32_t*>(&Bh[nrow*AST + kcol + 8]);
                bl[nt][0] = *reinterpret_cast<const uint32_t*>(&Bl[nrow*AST + kcol]);
                bl[nt][1] = *reinterpret_cast<const uint32_t*>(&Bl[nrow*AST + kcol + 8]);
            }
#pragma unroll
            for (int mt = 0; mt < 4; mt++) {
                int mrow = wr*64 + mt*16 + g;
                uint32_t ah[4], al[4];
                ah[0] = *reinterpret_cast<const uint32_t*>(&Ah[mrow*AST + kcol]);
                ah[1] = *reinterpret_cast<const uint32_t*>(&Ah[(mrow+8)*AST + kcol]);
                ah[2] = *reinterpret_cast<const uint32_t*>(&Ah[mrow*AST + kcol + 8]);
                ah[3] = *reinterpret_cast<const uint32_t*>(&Ah[(mrow+8)*AST + kcol + 8]);
                al[0] = *reinterpret_cast<const uint32_t*>(&Al[mrow*AST + kcol]);
                al[1] = *reinterpret_cast<const uint32_t*>(&Al[(mrow+8)*AST + kcol]);
                al[2] = *reinterpret_cast<const uint32_t*>(&Al[mrow*AST + kcol + 8]);
                al[3] = *reinterpret_cast<const uint32_t*>(&Al[(mrow+8)*AST + kcol + 8]);
#pragma unroll
                for (int nt = 0; nt < 4; nt++) {
                    mma16816(acc[mt][nt], ah, bh[nt]);
                    mma16816(acc[mt][nt], ah, bl[nt]);
                    mma16816(acc[mt][nt], al, bh[nt]);
                }
            }
        }
        __syncthreads();
    }

#pragma unroll
    for (int mt = 0; mt < 4; mt++) {
        int row = m0 + wr*64 + mt*16 + g;
#pragma unroll
        for (int nt = 0; nt < 4; nt++) {
            int col = n0 + wc*32 + nt*8 + tq*2;
            if (col < N) {
                *reinterpret_cast<float2*>(&C[(size_t)row*ldc + col]) =
                    make_float2(acc[mt][nt][0], acc[mt][nt][1]);
                *reinterpret_cast<float2*>(&C[(size_t)(row+8)*ldc + col]) =
                    make_float2(acc[mt][nt][2], acc[mt][nt][3]);
            }
        }
    }
}

// ------------------------------ rmsnorm ------------------------------------
__global__ void rmsnorm_kernel(float* __restrict__ x, const float* __restrict__ w,
                               int dim, int stride)
{
    const int row = blockIdx.x;
    float* xr = x + (size_t)row * stride;
    float ss = 0.f;
    for (int d = threadIdx.x; d < dim; d += blockDim.x) { float v = xr[d]; ss += v*v; }
    __shared__ float red[8];
#pragma unroll
    for (int o = 16; o > 0; o >>= 1) ss += __shfl_xor_sync(0xffffffffu, ss, o);
    if ((threadIdx.x & 31) == 0) red[threadIdx.x >> 5] = ss;
    __syncthreads();
    if (threadIdx.x == 0) {
        float v = 0.f;
        for (int i = 0; i < (int)(blockDim.x >> 5); i++) v += red[i];
        red[0] = v;
    }
    __syncthreads();
    const float scale = rsqrtf(red[0] / (float)dim + 1e-6f);
    for (int d = threadIdx.x; d < dim; d += blockDim.x) xr[d] = xr[d] * scale * w[d];
}

// ------------------------------ RoPE kernels -------------------------------
__global__ void rope_q_kernel(float* __restrict__ q, const float* __restrict__ cs,
                              const float* __restrict__ sn)
{
    int idx = blockIdx.x * blockDim.x + threadIdx.x;
    if (idx >= S_ * H_ * 32) return;
    int d = idx & 31, h = (idx >> 5) & 15, s = idx >> 9;
    float c = cs[s*32 + d], si = sn[s*32 + d];
    float* p = q + (size_t)s*3072 + h*192 + 128 + 2*d;
    float xr = p[0], xi = p[1];
    p[0] = xr*c - xi*si;
    p[1] = xr*si + xi*c;
}

__global__ void rope_k_kernel(const float* __restrict__ kv, float* __restrict__ kr,
                              const float* __restrict__ cs, const float* __restrict__ sn)
{
    int idx = blockIdx.x * blockDim.x + threadIdx.x;
    if (idx >= S_ * 32) return;
    int d = idx & 31, s = idx >> 5;
    float c = cs[s*32 + d], si = sn[s*32 + d];
    const float* p = kv + (size_t)s*576 + 512 + 2*d;
    float xr = p[0], xi = p[1];
    kr[(size_t)s*64 + 2*d]     = xr*c - xi*si;
    kr[(size_t)s*64 + 2*d + 1] = xr*si + xi*c;
}

__global__ void rope_qi_kernel(float* __restrict__ qi, const float* __restrict__ cs,
                               const float* __restrict__ sn)
{
    int idx = blockIdx.x * blockDim.x + threadIdx.x;
    if (idx >= S_ * 16 * 32) return;
    int d = idx & 31, n = (idx >> 5) & 15, s = idx >> 9;
    float c = cs[s*32 + d], si = sn[s*32 + d];
    float* p = qi + (size_t)s*2048 + n*128;
    float xr = p[d], xi = p[32 + d];
    p[d]      = xr*c - xi*si;
    p[32 + d] = xr*si + xi*c;
}

__global__ void ki_lnrope_kernel(const float* __restrict__ comb, float* __restrict__ ki,
                                 float* __restrict__ wts,
                                 const float* __restrict__ w, const float* __restrict__ b,
                                 const float* __restrict__ cs, const float* __restrict__ sn)
{
    const int s = blockIdx.x, t = threadIdx.x;
    const float* rowc = comb + (size_t)s*144;
    float* rowo = ki + (size_t)s*128;
    if (t < 16) wts[(size_t)s*16 + t] = rowc[128 + t];
    __shared__ float sh[128];
    __shared__ float warpred[4];
    __shared__ float s_mu, s_rstd;
    float v = rowc[t];
    float x = v;
#pragma unroll
    for (int o = 16; o > 0; o >>= 1) x += __shfl_xor_sync(0xffffffffu, x, o);
    if ((t & 31) == 0) warpred[t >> 5] = x;
    __syncthreads();
    if (t == 0) s_mu = (warpred[0]+warpred[1]+warpred[2]+warpred[3]) * (1.f/128.f);
    __syncthreads();
    float mu = s_mu;
    float dv = v - mu;
    float y = dv*dv;
#pragma unroll
    for (int o = 16; o > 0; o >>= 1) y += __shfl_xor_sync(0xffffffffu, y, o);
    if ((t & 31) == 0) warpred[t >> 5] = y;
    __syncthreads();
    if (t == 0) s_rstd = rsqrtf((warpred[0]+warpred[1]+warpred[2]+warpred[3]) * (1.f/128.f) + 1e-5f);
    __syncthreads();
    float nv = dv * s_rstd * w[t] + b[t];
    sh[t] = nv;
    __syncthreads();
    float outv;
    if (t < 32) {
        float c = cs[s*32 + t], si = sn[s*32 + t];
        outv = sh[t]*c - sh[t+32]*si;
    } else if (t < 64) {
        int d = t - 32;
        float c = cs[s*32 + d], si = sn[s*32 + d];
        outv = sh[d]*si + sh[t]*c;
    } else outv = nv;
    rowo[t] = outv;
}

// --------------------------- indexer scores --------------------------------
__global__ void __launch_bounds__(256) indexer_kernel(
    const float* __restrict__ qi, const float* __restrict__ ki,
    const float* __restrict__ wts, float* __restrict__ isc, int q_off)
{
    const int k0 = blockIdx.x * 64;
    const int q0 = q_off + blockIdx.y * 32;
    if (k0 > q0 + 31) return;
    extern __shared__ float ism[];
    float* kis = ism;
    float* qis = ism + 64*132;
    const int tid = threadIdx.x;
    const int ql = tid & 15;
    const int kg = tid >> 4;

#pragma unroll
    for (int e = tid; e < 64*32; e += 256) {
        int r = e >> 5, d4 = e & 31;
        *reinterpret_cast<float4*>(&kis[r*132 + d4*4]) =
            *reinterpret_cast<const float4*>(&ki[(size_t)(k0+r)*128 + d4*4]);
    }
    float acc[2][4];
#pragma unroll
    for (int r = 0; r < 2; r++)
#pragma unroll
        for (int j = 0; j < 4; j++) acc[r][j] = 0.f;

    for (int n = 0; n < 16; n++) {
        __syncthreads();
#pragma unroll
        for (int e = tid; e < 32*32; e += 256) {
            int r = e >> 5, d4 = e & 31;
            *reinterpret_cast<float4*>(&qis[r*132 + d4*4]) =
                *reinterpret_cast<const float4*>(&qi[(size_t)(q0+r)*2048 + n*128 + d4*4]);
        }
        __syncthreads();
        float dots[2][4];
#pragma unroll
        for (int r = 0; r < 2; r++)
#pragma unroll
            for (int j = 0; j < 4; j++) dots[r][j] = 0.f;
#pragma unroll 4
        for (int d4 = 0; d4 < 32; d4++) {
            float4 qv0 = *reinterpret_cast<const float4*>(&qis[(ql*2+0)*132 + d4*4]);
            float4 qv1 = *reinterpret_cast<const float4*>(&qis[(ql*2+1)*132 + d4*4]);
#pragma unroll
            for (int j = 0; j < 4; j++) {
                float4 kv = *reinterpret_cast<const float4*>(&kis[(kg*4+j)*132 + d4*4]);
                dots[0][j] += qv0.x*kv.x + qv0.y*kv.y + qv0.z*kv.z + qv0.w*kv.w;
                dots[1][j] += qv1.x*kv.x + qv1.y*kv.y + qv1.z*kv.z + qv1.w*kv.w;
            }
        }
        float w0 = wts[(size_t)(q0+ql*2+0)*16 + n] * 0.25f;
        float w1 = wts[(size_t)(q0+ql*2+1)*16 + n] * 0.25f;
#pragma unroll
        for (int j = 0; j < 4; j++) {
            acc[0][j] += fmaxf(dots[0][j] * 0.08838834764831845f, 0.f) * w0;
            acc[1][j] += fmaxf(dots[1][j] * 0.08838834764831845f, 0.f) * w1;
        }
    }
#pragma unroll
    for (int r = 0; r < 2; r++) {
        int q = q0 + ql*2 + r;
#pragma unroll
        for (int j = 0; j < 4; j++) {
            int k = k0 + kg*4 + j;
            isc[(size_t)q*2048 + k] = (k <= q) ? acc[r][j] : -1e30f;
        }
    }
}

// ------------------------------ top-k mask ----------------------------------
__global__ void __launch_bounds__(256) topk_kernel(
    const float* __restrict__ isc, unsigned char* __restrict__ mask, int q_base)
{
    const int q = q_base + blockIdx.x;
    const int n = q + 1;
    const int tid = threadIdx.x;
    unsigned char* mrow = mask + (size_t)q * 2048;
    if (n <= TOPK_) {
        for (int k = tid; k < 2048; k += 256) mrow[k] = (k <= q) ? 1 : 0;
        return;
    }
    __shared__ unsigned int keys[2048];
    __shared__ unsigned int hist[256];
    __shared__ unsigned int suf[2][256];
    __shared__ int s_d;
    __shared__ int s_cnt, s_eq;
    const float* row = isc + (size_t)q * 2048;
    for (int k = tid; k < n; k += 256) {
        unsigned int bb = __float_as_uint(row[k]);
        keys[k] = (bb & 0x80000000u) ? ~bb : (bb | 0x80000000u);
    }
    __syncthreads();

    unsigned int prefix = 0;
    int kth = TOPK_;
#pragma unroll
    for (int pass = 0; pass < 4; pass++) {
        const int shift = 24 - pass*8;
        const unsigned int hm = (pass == 0) ? 0u : (~0u << (shift + 8));
        hist[tid] = 0;
        __syncthreads();
        for (int k = tid; k < n; k += 256) {
            unsigned int key = keys[k];
            if ((key & hm) == prefix) atomicAdd(&hist[(key >> shift) & 255], 1u);
        }
        __syncthreads();
        suf[0][tid] = hist[tid];
        __syncthreads();
        int sb = 0;
#pragma unroll
        for (int off = 1; off < 256; off <<= 1) {
            unsigned int v = suf[sb][tid] + ((tid + off < 256) ? suf[sb][tid + off] : 0u);
            suf[sb ^ 1][tid] = v;
            __syncthreads();
            sb ^= 1;
        }
        const unsigned int* Ssum = suf[sb];
        if (Ssum[tid] >= (unsigned int)kth &&
            (tid == 255 || Ssum[tid + 1] < (unsigned int)kth)) s_d = tid;
        __syncthreads();
        const int d = s_d;
        const int cnt_gt = (d == 255) ? 0 : (int)Ssum[d + 1];
        kth -= cnt_gt;
        prefix |= ((unsigned int)d) << shift;
        __syncthreads();
    }

    const unsigned int T = prefix;
    if (tid == 0) { s_cnt = 0; s_eq = 0; }
    __syncthreads();
    int cg = 0, ce = 0;
    for (int k = tid; k < n; k += 256) {
        unsigned int key = keys[k];
        if (key > T) cg++;
        else if (key == T) ce++;
    }
#pragma unroll
    for (int o = 16; o > 0; o >>= 1) {
        cg += __shfl_xor_sync(0xffffffffu, cg, o);
        ce += __shfl_xor_sync(0xffffffffu, ce, o);
    }
    if ((tid & 31) == 0) { atomicAdd(&s_cnt, cg); atomicAdd(&s_eq, ce); }
    __syncthreads();
    const int ngt = s_cnt, neq = s_eq;
    const int take_eq = TOPK_ - ngt;
    if (take_eq >= neq) {
        for (int k = tid; k < 2048; k += 256)
            mrow[k] = (k < n && keys[k] >= T) ? 1 : 0;
    } else {
        for (int k = tid; k < 2048; k += 256)
            mrow[k] = (k < n && keys[k] > T) ? 1 : 0;
        __syncthreads();
        if (tid == 0) {
            int c = 0;
            for (int k = 0; k < n && c < take_eq; k++)
                if (keys[k] == T) { mrow[k] = 1; c++; }
        }
    }
}

// --------------------------- flash attention (FFMA2) ------------------------
#define FL_QN 132
#define FL_QR 68
__global__ void __launch_bounds__(256) flash_kernel(
    const float* __restrict__ qb, const float* __restrict__ kvb,
    const float* __restrict__ krope, const unsigned char* __restrict__ msk,
    float* __restrict__ attn, int q_base)
{
    const int h  = blockIdx.y;
    const int q0 = q_base + (gridDim.x - 1 - blockIdx.x) * 64;
    extern __shared__ float smf[];
    float* qn = smf;
    float* qr = qn + 64*FL_QN;
    float* kn = qr + 64*FL_QR;
    float* kr = kn + 32*FL_QN;
    float* vs = kr + 32*FL_QR;
    float* pr = vs + 32*FL_QN;
    unsigned int* um = (unsigned int*)(pr + 64*33);

    const int tid = threadIdx.x;
    const int ql = tid >> 2;
    const int t  = tid & 3;

#pragma unroll
    for (int e = tid; e < 64*32; e += 256) {
        int r = e >> 5, d4 = e & 31;
        *reinterpret_cast<float4*>(&qn[r*FL_QN + d4*4]) =
            *reinterpret_cast<const float4*>(&qb[(size_t)(q0+r)*3072 + h*192 + d4*4]);
    }
#pragma unroll
    for (int e = tid; e < 64*16; e += 256) {
        int r = e >> 4, d4 = e & 15;
        *reinterpret_cast<float4*>(&qr[r*FL_QR + d4*4]) =
            *reinterpret_cast<const float4*>(&qb[(size_t)(q0+r)*3072 + h*192 + 128 + d4*4]);
    }

    float m = -INFINITY, l = 0.f;
    unsigned long long o2[16];
#pragma unroll
    for (int i = 0; i < 16; i++) o2[i] = 0ull;

    const int kend = q0 + 64;
    for (int k0 = 0; k0 < kend; k0 += 32) {
        __syncthreads();
#pragma unroll
        for (int e = tid; e < 32*32; e += 256) {
            int r = e >> 5, d4 = e & 31;
            *reinterpret_cast<float4*>(&kn[r*FL_QN + d4*4]) =
                *reinterpret_cast<const float4*>(&kvb[(size_t)(k0+r)*4096 + h*256 + d4*4]);
            *reinterpret_cast<float4*>(&vs[r*FL_QN + d4*4]) =
                *reinterpret_cast<const float4*>(&kvb[(size_t)(k0+r)*4096 + h*256 + 128 + d4*4]);
        }
#pragma unroll
        for (int e = tid; e < 32*16; e += 256) {
            int r = e >> 4, d4 = e & 15;
            *reinterpret_cast<float4*>(&kr[r*FL_QR + d4*4]) =
                *reinterpret_cast<const float4*>(&krope[(size_t)(k0+r)*64 + d4*4]);
        }
#pragma unroll
        for (int e = tid; e < 512; e += 256) {
            int r = e >> 3, c = e & 7;
            um[r*8 + c] = *reinterpret_cast<const unsigned int*>(
                &msk[(size_t)(q0+r)*2048 + k0 + c*4]);
        }
        __syncthreads();

        unsigned long long s2[8];
#pragma unroll
        for (int j = 0; j < 8; j++) s2[j] = 0ull;
#pragma unroll 4
        for (int d4 = 0; d4 < 32; d4++) {
            float4 qv = *reinterpret_cast<const float4*>(&qn[ql*FL_QN + d4*4]);
            unsigned long long qa = packf2(qv.x, qv.y), qc = packf2(qv.z, qv.w);
#pragma unroll
            for (int j = 0; j < 8; j++) {
                float4 kv = *reinterpret_cast<const float4*>(&kn[(j*4+t)*FL_QN + d4*4]);
                ffma2(s2[j], qa, packf2(kv.x, kv.y));
                ffma2(s2[j], qc, packf2(kv.z, kv.w));
            }
        }
#pragma unroll 4
        for (int d4 = 0; d4 < 16; d4++) {
            float4 qv = *reinterpret_cast<const float4*>(&qr[ql*FL_QR + d4*4]);
            unsigned long long qa = packf2(qv.x, qv.y), qc = packf2(qv.z, qv.w);
#pragma unroll
            for (int j = 0; j < 8; j++) {
                float4 kv = *reinterpret_cast<const float4*>(&kr[(j*4+t)*FL_QR + d4*4]);
                ffma2(s2[j], qa, packf2(kv.x, kv.y));
                ffma2(s2[j], qc, packf2(kv.z, kv.w));
            }
        }
        float s[8];
#pragma unroll
        for (int j = 0; j < 8; j++) {
            float lo, hi;
            unpackf2(s2[j], lo, hi);
            s[j] = lo + hi;
        }
        const int qg = q0 + ql;
        const unsigned char* umb = (const unsigned char*)um;
#pragma unroll
        for (int j = 0; j < 8; j++) {
            int kl = j*4 + t;
            bool ok = (k0 + kl <= qg) && umb[ql*32 + kl];
            s[j] = ok ? s[j] * 0.07216878364870323f : -INFINITY;
        }
        float mt = s[0];
#pragma unroll
        for (int j = 1; j < 8; j++) mt = fmaxf(mt, s[j]);
        mt = fmaxf(mt, __shfl_xor_sync(0xffffffffu, mt, 1));
        mt = fmaxf(mt, __shfl_xor_sync(0xffffffffu, mt, 2));
        float mn  = fmaxf(m, mt);
        float mns = (mn > -INFINITY) ? mn : 0.f;
        float alpha = (m > -INFINITY) ? __expf(m - mns) : 0.f;
        float ls = 0.f;
#pragma unroll
        for (int j = 0; j < 8; j++) {
            float p = (s[j] > -INFINITY) ? __expf(s[j] - mns) : 0.f;
            pr[ql*33 + j*4 + t] = p;
            ls += p;
        }
        ls += __shfl_xor_sync(0xffffffffu, ls, 1);
        ls += __shfl_xor_sync(0xffffffffu, ls, 2);
        l = l * alpha + ls;
        m = mn;
        unsigned long long al2 = packf2(alpha, alpha);
#pragma unroll
        for (int i = 0; i < 16; i++) mulf2(o2[i], al2);
        __syncwarp();
#pragma unroll 4
        for (int kk = 0; kk < 32; kk++) {
            float p = pr[ql*33 + kk];
            unsigned long long pp = packf2(p, p);
#pragma unroll
            for (int g = 0; g < 8; g++) {
                float4 v4 = *reinterpret_cast<const float4*>(&vs[kk*FL_QN + g*16 + t*4]);
                ffma2(o2[g*2],     pp, packf2(v4.x, v4.y));
                ffma2(o2[g*2 + 1], pp, packf2(v4.z, v4.w));
            }
        }
    }
    const float inv = 1.f / l;
#pragma unroll
    for (int g = 0; g < 8; g++) {
        float o0, o1, o2v, o3;
        unpackf2(o2[g*2],     o0, o1);
        unpackf2(o2[g*2 + 1], o2v, o3);
        float* dst = &attn[(size_t)(q0+ql)*2048 + h*128 + g*16 + t*4];
        dst[0] = o0 * inv; dst[1] = o1 * inv;
        dst[2] = o2v * inv; dst[3] = o3 * inv;
    }
}

// ------------------------------ launch -------------------------------------
extern "C" void kernel_launch(void* const* d_in, const int* in_sizes, int n_in,
                              void* d_out, int out_size)
{
    const float* hidden     = (const float*)d_in[0];
    const float* cosb       = (const float*)d_in[1];
    const float* sinb       = (const float*)d_in[2];
    const float* w_q_a      = (const float*)d_in[3];
    const float* q_a_ln_w   = (const float*)d_in[4];
    const float* w_q_b      = (const float*)d_in[5];
    const float* w_kv_a     = (const float*)d_in[6];
    const float* kv_a_ln_w  = (const float*)d_in[7];
    const float* w_kv_b     = (const float*)d_in[8];
    const float* w_o        = (const float*)d_in[9];
    const float* idx_wq_b   = (const float*)d_in[10];
    const float* idx_wk     = (const float*)d_in[11];
    const float* idx_k_ln_w = (const float*)d_in[12];
    const float* idx_k_ln_b = (const float*)d_in[13];
    const float* idx_w_proj = (const float*)d_in[14];
    float* out = (float*)d_out;

    float *cq, *qbp, *kv, *krope, *kvb, *qi, *ki, *wts, *isc, *attn, *wcomb, *kicomb;
    unsigned char* msk;
    cudaGetSymbolAddress((void**)&cq,    g_cq);
    cudaGetSymbolAddress((void**)&qbp,   g_q);
    cudaGetSymbolAddress((void**)&kv,    g_kv);
    cudaGetSymbolAddress((void**)&krope, g_krope);
    cudaGetSymbolAddress((void**)&kvb,   g_kvb);
    cudaGetSymbolAddress((void**)&qi,    g_qi);
    cudaGetSymbolAddress((void**)&ki,    g_ki);
    cudaGetSymbolAddress((void**)&wts,   g_wts);
    cudaGetSymbolAddress((void**)&isc,   g_isc);
    cudaGetSymbolAddress((void**)&msk,   g_mask);
    cudaGetSymbolAddress((void**)&attn,  g_attn);
    cudaGetSymbolAddress((void**)&wcomb, g_wcomb);
    cudaGetSymbolAddress((void**)&kicomb,g_kicomb);

    __nv_bfloat16 *H0,*H1,*CQ0,*CQ1,*KV0,*KV1,*AT0,*AT1;
    __nv_bfloat16 *Wkva0,*Wkva1,*Wqb0,*Wqb1,*Wkvb0,*Wkvb1,*Wo0,*Wo1;
    cudaGetSymbolAddress((void**)&H0,  g_H0);   cudaGetSymbolAddress((void**)&H1,  g_H1);
    cudaGetSymbolAddress((void**)&CQ0, g_CQ0);  cudaGetSymbolAddress((void**)&CQ1, g_CQ1);
    cudaGetSymbolAddress((void**)&KV0, g_KV0);  cudaGetSymbolAddress((void**)&KV1, g_KV1);
    cudaGetSymbolAddress((void**)&AT0, g_AT0);  cudaGetSymbolAddress((void**)&AT1, g_AT1);
    cudaGetSymbolAddress((void**)&Wkva0,g_Wkva0); cudaGetSymbolAddress((void**)&Wkva1,g_Wkva1);
    cudaGetSymbolAddress((void**)&Wqb0, g_Wqb0); cudaGetSymbolAddress((void**)&Wqb1, g_Wqb1);
    cudaGetSymbolAddress((void**)&Wkvb0,g_Wkvb0); cudaGetSymbolAddress((void**)&Wkvb1,g_Wkvb1);
    cudaGetSymbolAddress((void**)&Wo0,  g_Wo0);  cudaGetSymbolAddress((void**)&Wo1,  g_Wo1);

    const int GSM2 = 8 * BUF_E * 2;        // 81920 B
    const int GSMF = 2 * F_STG * 4;        // 36864 B
    const int ISM  = (64 + 32) * 132 * 4;  // 50688 B
    cudaFuncSetAttribute(gemm_mma2, cudaFuncAttributeMaxDynamicSharedMemorySize, GSM2);
    cudaFuncSetAttribute(gemm_f32,  cudaFuncAttributeMaxDynamicSharedMemorySize, GSMF);
    cudaFuncSetAttribute(indexer_kernel, cudaFuncAttributeMaxDynamicSharedMemorySize, ISM);

    const dim3 blk(256);
    const dim3 tb(32, 8);
    cudaStream_t s1 = g_si.s1, s2 = g_si.s2;

    // ---- fork ----
    cudaEventRecord(g_si.ev0, 0);
    cudaStreamWaitEvent(s1, g_si.ev0, 0);
    cudaStreamWaitEvent(s2, g_si.ev0, 0);

    // ======== s2: ki/wts chain (independent of cq) ========
    pack_wik<<<(4096*144 + 255)/256, 256, 0, s2>>>(idx_wk, idx_w_proj, wcomb);
    gemm_f32_m32<<<dim3(2, 64), blk, 0, s2>>>(hidden, wcomb, kicomb, 2048, 144, 4096, 4096, 144);
    ki_lnrope_kernel<<<2048, 128, 0, s2>>>(kicomb, ki, wts, idx_k_ln_w, idx_k_ln_b, cosb, sinb);
    cudaEventRecord(g_si.ev_ki, s2);

    // ======== default: cq -> qi(full) -> indexer-high -> topk-high ========
    gemm_f32<<<dim3(12, 16), blk, GSMF>>>(hidden, w_q_a, cq, 2048, 1536, 4096, 4096);
    rmsnorm_kernel<<<2048, 256>>>(cq, q_a_ln_w, 1536, 1536);
    cudaEventRecord(g_si.ev_cq, 0);
    gemm_f32<<<dim3(16, 16), blk, GSMF>>>(cq, idx_wq_b, qi, 2048, 2048, 1536, 1536);
    rope_qi_kernel<<<(2048*16*32)/256, 256>>>(qi, cosb, sinb);
    cudaEventRecord(g_si.ev_qi, 0);
    cudaStreamWaitEvent(0, g_si.ev_ki, 0);
    indexer_kernel<<<dim3(32, 48), blk, ISM>>>(qi, ki, wts, isc, 512);
    topk_kernel<<<1536, 256>>>(isc, msk, 512);

    // ======== s2: low-q indexer/topk (6% of work; after qi + ki in-order) ====
    cudaStreamWaitEvent(s2, g_si.ev_qi, 0);
    indexer_kernel<<<dim3(8, 16), blk, ISM, s2>>>(qi, ki, wts, isc, 0);
    topk_kernel<<<512, 256, 0, s2>>>(isc, msk, 0);
    cudaEventRecord(g_si.ev_tkB, s2);

    // ======== s1: value path (overlaps indexer chain) ========
    act_conv<<<(2048*2048+255)/256, 256, 0, s1>>>(hidden, H0, H1, 2048, 2048, 4096);
    wconv_t<<<dim3(640/32,  4096/32), tb, 0, s1>>>(w_kv_a, Wkva0, Wkva1, 4096, 576);
    wconv_t<<<dim3(3072/32, 1536/32), tb, 0, s1>>>(w_q_b,  Wqb0,  Wqb1,  1536, 3072);
    wconv_t<<<dim3(4096/32, 512/32),  tb, 0, s1>>>(w_kv_b, Wkvb0, Wkvb1, 512,  4096);
    wconv_t<<<dim3(4096/32, 2048/32), tb, 0, s1>>>(w_o,    Wo0,   Wo1,   2048, 4096);
    gemm_mma2<<<dim3(5, 16), blk, GSM2, s1>>>(H0, H1, Wkva0, Wkva1, kv, 576, 4096, 576);
    rope_k_kernel<<<(2048*32)/256, 256, 0, s1>>>(kv, krope, cosb, sinb);
    rmsnorm_kernel<<<2048, 256, 0, s1>>>(kv, kv_a_ln_w, 512, 576);
    act_conv<<<(2048*256+255)/256, 256, 0, s1>>>(kv, KV0, KV1, 2048, 256, 576);
    gemm_mma2<<<dim3(32, 16), blk, GSM2, s1>>>(KV0, KV1, Wkvb0, Wkvb1, kvb, 4096, 512, 4096);
    cudaStreamWaitEvent(s1, g_si.ev_cq, 0);
    act_conv<<<(2048*768+255)/256, 256, 0, s1>>>(cq, CQ0, CQ1, 2048, 768, 1536);
    gemm_mma2<<<dim3(24, 16), blk, GSM2, s1>>>(CQ0, CQ1, Wqb0, Wqb1, qbp, 3072, 1536, 3072);
    rope_q_kernel<<<(2048*16*32)/256, 256, 0, s1>>>(qbp, cosb, sinb);
    cudaEventRecord(g_si.ev_val, s1);

    // ---- flashA (q >= 512) on default; flashB (q < 512) CONCURRENT on s1 ----
    cudaStreamWaitEvent(0, g_si.ev_val, 0);
    const int FLASH_SMEM = (64*FL_QN + 64*FL_QR + 32*FL_QN + 32*FL_QR + 32*FL_QN + 64*33)*4
                           + 64*32;
    cudaFuncSetAttribute(flash_kernel, cudaFuncAttributeMaxDynamicSharedMemorySize, FLASH_SMEM);
    flash_kernel<<<dim3(24, 16), blk, FLASH_SMEM>>>(qbp, kvb, krope, msk, attn, 512);

    cudaStreamWaitEvent(s1, g_si.ev_tkB, 0);
    flash_kernel<<<dim3(8, 16), blk, FLASH_SMEM, s1>>>(qbp, kvb, krope, msk, attn, 0);
    cudaEventRecord(g_si.ev_fb, s1);

    // default: w_o high (rows 512..2047) right after flashA
    act_conv<<<(1536*1024+255)/256, 256>>>(attn + (size_t)512*2048,
                                           AT0 + (size_t)512*2048,
                                           AT1 + (size_t)512*2048, 1536, 1024, 2048);
    gemm_mma2<<<dim3(32, 12), blk, GSM2>>>(AT0 + (size_t)512*2048, AT1 + (size_t)512*2048,
                                           Wo0, Wo1, out + (size_t)512*4096,
                                           4096, 2048, 4096);

    // s2: w_o low (rows 0..511) after flashB, concurrent with w_o high
    cudaStreamWaitEvent(s2, g_si.ev_fb, 0);
    act_conv<<<(512*1024+255)/256, 256, 0, s2>>>(attn, AT0, AT1, 512, 1024, 2048);
    gemm_mma2<<<dim3(32, 4), blk, GSM2, s2>>>(AT0, AT1, Wo0, Wo1, out, 4096, 2048, 4096);
    cudaEventRecord(g_si.ev_woB, s2);

    cudaStreamWaitEvent(0, g_si.ev_woB, 0);
}